// round 16
// baseline (speedup 1.0000x reference)
#include <cuda_runtime.h>

// ---------------------------------------------------------------------------
// StructureAwareAttention on GB300 — Round 16: LDS/barrier-lean tf32 GEMMs
//   * weights pre-converted to tf32 once (cvtw_kernel) -> B frags via LDG (L1)
//   * no sW smem staging -> syncthreads per block: 18 -> 4
//   * qkv warp tile m32xn64 (B-frag reuse x2); out_ln keeps m16xn128 for LN
//   N=50000 nodes, C=128, E=800000 edges, HEADS=4, HEAD_DIM=32
// ---------------------------------------------------------------------------

#define NMAX 50000
#define EMAX 800000
#define SCAN_B 1024

__device__ float    g_q[(size_t)NMAX * 128];
__device__ unsigned g_kh[(size_t)NMAX * 64];   // 64 f16x2 words per row
__device__ unsigned g_vh[(size_t)NMAX * 64];
__device__ float    g_att[(size_t)NMAX * 128];
__device__ int      g_cnt[NMAX];
__device__ int      g_off[NMAX + 1];
__device__ int      g_cur[NMAX];
__device__ int      g_packed[EMAX];
__device__ int      g_bsum[64];
__device__ int      g_boff[64];
// tf32-preconverted weights (128x128 each)
__device__ float    g_wq[16384];
__device__ float    g_wk[16384];
__device__ float    g_wv[16384];
__device__ float    g_wo[16384];

// ---------------------------------------------------------------- helpers
__device__ __forceinline__ float tf32r(float f) {
    unsigned u;
    asm("cvt.rna.tf32.f32 %0, %1;" : "=r"(u) : "f"(f));
    return __uint_as_float(u);
}

__device__ __forceinline__ void mma_tf32(float* d,
    unsigned a0, unsigned a1, unsigned a2, unsigned a3,
    unsigned b0, unsigned b1)
{
    asm volatile(
        "mma.sync.aligned.m16n8k8.row.col.f32.tf32.tf32.f32 "
        "{%0,%1,%2,%3}, {%4,%5,%6,%7}, {%8,%9}, {%0,%1,%2,%3};"
        : "+f"(d[0]), "+f"(d[1]), "+f"(d[2]), "+f"(d[3])
        : "r"(a0), "r"(a1), "r"(a2), "r"(a3), "r"(b0), "r"(b1));
}

// pack two fp32 -> one f16x2 word (lo = first arg, hi = second arg)
__device__ __forceinline__ unsigned pack_h2(float lo, float hi) {
    unsigned u;
    asm("cvt.rn.f16x2.f32 %0, %1, %2;" : "=r"(u) : "f"(hi), "f"(lo));
    return u;
}

// unpack f16x2 word -> two fp32
__device__ __forceinline__ float2 unpack_h2(unsigned u) {
    float2 r;
    asm("{\n\t"
        ".reg .b16 l, h;\n\t"
        "mov.b32 {l, h}, %2;\n\t"
        "cvt.f32.f16 %0, l;\n\t"
        "cvt.f32.f16 %1, h;\n\t"
        "}"
        : "=f"(r.x), "=f"(r.y) : "r"(u));
    return r;
}

// SMEM stride for conflict-free A-fragment LDS:
//   XS=68 (= 4 mod 32): A-frag bank = (lane>>2)*4 + (lane&3) -> bijection
#define XS 68

// ---------------------------------------------------------------- K0: zero
__global__ void zero_cnt_kernel(int n) {
    int i = blockIdx.x * blockDim.x + threadIdx.x;
    if (i < n) g_cnt[i] = 0;
}

// ---------------------------------------------------------------- KW: pre-convert weights to tf32
__global__ void cvtw_kernel(const float* __restrict__ Wq,
                            const float* __restrict__ Wk,
                            const float* __restrict__ Wv,
                            const float* __restrict__ Wo) {
    int i = blockIdx.x * blockDim.x + threadIdx.x;
    if (i < 16384) {
        g_wq[i] = tf32r(Wq[i]);
        g_wk[i] = tf32r(Wk[i]);
        g_wv[i] = tf32r(Wv[i]);
        g_wo[i] = tf32r(Wo[i]);
    }
}

// ---------------------------------------------------------------- K1: QKV GEMM (tf32 MMA)
// 256 thr / 8 warps. Warp (mw = warp>>1, nw = warp&1):
//   rows [128*bx + 32*mw, +32) (two m16 tiles), cols [64*nw, +64) (8 n8 tiles).
// B frags straight from pre-converted tf32 W in gmem (L1-resident, 64KB).
// blockIdx.y: 0 -> Q (fp32 out), 1 -> K (f16x2 out), 2 -> V (f16x2 out)
__global__ __launch_bounds__(256, 2) void qkv_gemm_kernel(
    const float* __restrict__ x,
    const float* __restrict__ bq,
    const float* __restrict__ bk,
    const float* __restrict__ bv,
    int n)
{
    __shared__ __align__(16) float sX[128][XS];

    const float* W; const float* bias;
    if (blockIdx.y == 0)      { W = g_wq; bias = bq; }
    else if (blockIdx.y == 1) { W = g_wk; bias = bk; }
    else                      { W = g_wv; bias = bv; }

    int tid  = threadIdx.x;
    int warp = tid >> 5, lane = tid & 31;
    int mw   = warp >> 1;      // 0..3
    int nw   = warp & 1;       // 0..1
    int row0 = blockIdx.x * 128;
    int qr   = lane >> 2;
    int qc   = lane & 3;

    float acc[2][8][4];
#pragma unroll
    for (int m = 0; m < 2; m++)
#pragma unroll
        for (int t = 0; t < 8; t++)
#pragma unroll
            for (int j = 0; j < 4; j++) acc[m][t][j] = 0.f;

    for (int kg0 = 0; kg0 < 128; kg0 += 64) {
        __syncthreads();
        // load X half-tile [128 rows x 64 cols], tf32-rounded (8 float4/thread)
#pragma unroll
        for (int t = 0; t < 8; t++) {
            int i = t * 256 + tid;
            int r = i >> 4, c4 = i & 15;
            float4 v = make_float4(0.f, 0.f, 0.f, 0.f);
            if (row0 + r < n)
                v = ((const float4*)x)[(size_t)(row0 + r) * 32 + (kg0 >> 2) + c4];
            v.x = tf32r(v.x); v.y = tf32r(v.y); v.z = tf32r(v.z); v.w = tf32r(v.w);
            *((float4*)&sX[r][0] + c4) = v;
        }
        __syncthreads();

#pragma unroll
        for (int k8 = 0; k8 < 64; k8 += 8) {
            // A frags for the warp's two m16 tiles
            unsigned a[2][4];
#pragma unroll
            for (int m = 0; m < 2; m++) {
                int rb = mw * 32 + m * 16;
                a[m][0] = __float_as_uint(sX[rb + qr][k8 + qc]);
                a[m][1] = __float_as_uint(sX[rb + qr + 8][k8 + qc]);
                a[m][2] = __float_as_uint(sX[rb + qr][k8 + qc + 4]);
                a[m][3] = __float_as_uint(sX[rb + qr + 8][k8 + qc + 4]);
            }
            int kg = kg0 + k8;
            const float* Wr0 = W + (size_t)(kg + qc) * 128 + nw * 64 + qr;
            const float* Wr1 = Wr0 + 4 * 128;
#pragma unroll
            for (int t = 0; t < 8; t++) {
                unsigned b0 = __float_as_uint(Wr0[t * 8]);
                unsigned b1 = __float_as_uint(Wr1[t * 8]);
                mma_tf32(acc[0][t], a[0][0], a[0][1], a[0][2], a[0][3], b0, b1);
                mma_tf32(acc[1][t], a[1][0], a[1][1], a[1][2], a[1][3], b0, b1);
            }
        }
    }

    // epilogue: + bias; Q -> fp32, K/V -> packed f16x2
    bool isQ = (blockIdx.y == 0);
    unsigned* outh = (blockIdx.y == 1) ? g_kh : g_vh;
#pragma unroll
    for (int t = 0; t < 8; t++) {
        int c = nw * 64 + t * 8 + qc * 2;
        float2 b2 = *(const float2*)&bias[c];
#pragma unroll
        for (int m = 0; m < 2; m++) {
            int rlo = row0 + mw * 32 + m * 16 + qr;
            int rhi = rlo + 8;
            float2 olo = make_float2(acc[m][t][0] + b2.x, acc[m][t][1] + b2.y);
            float2 ohi = make_float2(acc[m][t][2] + b2.x, acc[m][t][3] + b2.y);
            if (isQ) {
                if (rlo < n) *(float2*)&g_q[(size_t)rlo * 128 + c] = olo;
                if (rhi < n) *(float2*)&g_q[(size_t)rhi * 128 + c] = ohi;
            } else {
                if (rlo < n) outh[(size_t)rlo * 64 + (c >> 1)] = pack_h2(olo.x, olo.y);
                if (rhi < n) outh[(size_t)rhi * 64 + (c >> 1)] = pack_h2(ohi.x, ohi.y);
            }
        }
    }
}

// ---------------------------------------------------------------- K2: histogram
__global__ void hist_kernel(const int* __restrict__ dst, int e) {
    int i = blockIdx.x * blockDim.x + threadIdx.x;
    if (i < e) atomicAdd(&g_cnt[dst[i]], 1);
}

// ---------------------------------------------------------------- S1: block scan
__global__ __launch_bounds__(SCAN_B) void scan1_kernel(int n) {
    __shared__ int wsum[32];
    int tid  = threadIdx.x;
    int lane = tid & 31, wid = tid >> 5;
    int i = blockIdx.x * SCAN_B + tid;
    int val = (i < n) ? g_cnt[i] : 0;

    int x = val;
#pragma unroll
    for (int d = 1; d < 32; d <<= 1) {
        int t = __shfl_up_sync(0xffffffffu, x, d);
        if (lane >= d) x += t;
    }
    if (lane == 31) wsum[wid] = x;
    __syncthreads();
    if (wid == 0) {
        int w = wsum[lane];
#pragma unroll
        for (int d = 1; d < 32; d <<= 1) {
            int t = __shfl_up_sync(0xffffffffu, w, d);
            if (lane >= d) w += t;
        }
        wsum[lane] = w;
    }
    __syncthreads();
    int base = (wid > 0) ? wsum[wid - 1] : 0;
    int incl = x + base;
    if (i < n) g_off[i] = incl - val;
    if (tid == SCAN_B - 1) g_bsum[blockIdx.x] = incl;
}

// ---------------------------------------------------------------- S2: scan blocks
__global__ void scan2_kernel(int nb, int n) {
    __shared__ int s[64];
    int tid = threadIdx.x;
    int val = (tid < nb) ? g_bsum[tid] : 0;
    s[tid] = val;
    __syncthreads();
#pragma unroll
    for (int d = 1; d < 64; d <<= 1) {
        int t = (tid >= d) ? s[tid - d] : 0;
        __syncthreads();
        s[tid] += t;
        __syncthreads();
    }
    if (tid < nb) g_boff[tid] = s[tid] - val;
    if (tid == 63) g_off[n] = s[63];
}

// ---------------------------------------------------------------- S3: add base
__global__ __launch_bounds__(SCAN_B) void scan3_kernel(int n) {
    int i = blockIdx.x * SCAN_B + threadIdx.x;
    if (i < n) {
        int v = g_off[i] + g_boff[blockIdx.x];
        g_off[i] = v;
        g_cur[i] = v;
    }
}

// ---------------------------------------------------------------- K4: scatter
__global__ void scatter_kernel(const int* __restrict__ src,
                               const int* __restrict__ dst,
                               const int* __restrict__ stype, int e) {
    int i = blockIdx.x * blockDim.x + threadIdx.x;
    if (i < e) {
        int d = dst[i];
        int p = atomicAdd(&g_cur[d], 1);
        int s_ = src[i];
        g_packed[p] = s_ | (stype[s_] << 20);
    }
}

// ---------------------------------------------------------------- K5: gather (R7 version)
// One warp per node. Lane l owns dims [4l,4l+4): one uint2 (4 halfs) per matrix.
__global__ __launch_bounds__(256) void gather_kernel(
    const float* __restrict__ sbias, int n)
{
    int node = (blockIdx.x * blockDim.x + threadIdx.x) >> 5;
    int lane = threadIdx.x & 31;
    if (node >= n) return;

    int head = lane >> 3;
    float b0 = sbias[0 * 4 + head];
    float b1 = sbias[1 * 4 + head];
    float b2 = sbias[2 * 4 + head];

    const uint2* kp = (const uint2*)g_kh;   // node row = 32 uint2
    const uint2* vp = (const uint2*)g_vh;
    float4 q4 = ((const float4*)g_q)[(size_t)node * 32 + lane];

    float4 acc = make_float4(0.f, 0.f, 0.f, 0.f);
    float ssum = 0.f;
    const float INV_SQRT_HD = 0.17677669529663689f;  // 1/sqrt(32)

    int beg = g_off[node], end = g_off[node + 1];
    int j = beg;
    for (; j + 1 < end; j += 2) {
        int w0 = g_packed[j], w1 = g_packed[j + 1];
        int s0 = w0 & 0xFFFFF, t0 = w0 >> 20;
        int s1 = w1 & 0xFFFFF, t1 = w1 >> 20;
        uint2 kw0 = kp[(size_t)s0 * 32 + lane];
        uint2 kw1 = kp[(size_t)s1 * 32 + lane];
        uint2 vw0 = vp[(size_t)s0 * 32 + lane];
        uint2 vw1 = vp[(size_t)s1 * 32 + lane];

        float2 ka0 = unpack_h2(kw0.x);
        float2 ka1 = unpack_h2(kw0.y);
        float2 kb0 = unpack_h2(kw1.x);
        float2 kb1 = unpack_h2(kw1.y);

        float pa = q4.x * ka0.x + q4.y * ka0.y + q4.z * ka1.x + q4.w * ka1.y;
        float pb = q4.x * kb0.x + q4.y * kb0.y + q4.z * kb1.x + q4.w * kb1.y;
        pa += __shfl_xor_sync(0xffffffffu, pa, 1);
        pb += __shfl_xor_sync(0xffffffffu, pb, 1);
        pa += __shfl_xor_sync(0xffffffffu, pa, 2);
        pb += __shfl_xor_sync(0xffffffffu, pb, 2);
        pa += __shfl_xor_sync(0xffffffffu, pa, 4);
        pb += __shfl_xor_sync(0xffffffffu, pb, 4);

        float ba = (t0 == 0) ? b0 : ((t0 == 1) ? b1 : b2);
        float bb = (t1 == 0) ? b0 : ((t1 == 1) ? b1 : b2);
        float ea = __expf(pa * INV_SQRT_HD + ba);
        float eb = __expf(pb * INV_SQRT_HD + bb);
        ssum += ea + eb;

        float2 va0 = unpack_h2(vw0.x);
        float2 va1 = unpack_h2(vw0.y);
        float2 vb0 = unpack_h2(vw1.x);
        float2 vb1 = unpack_h2(vw1.y);
        acc.x += ea * va0.x + eb * vb0.x;
        acc.y += ea * va0.y + eb * vb0.y;
        acc.z += ea * va1.x + eb * vb1.x;
        acc.w += ea * va1.y + eb * vb1.y;
    }
    if (j < end) {
        int w0 = g_packed[j];
        int s0 = w0 & 0xFFFFF, t0 = w0 >> 20;
        uint2 kw0 = kp[(size_t)s0 * 32 + lane];
        uint2 vw0 = vp[(size_t)s0 * 32 + lane];
        float2 ka0 = unpack_h2(kw0.x);
        float2 ka1 = unpack_h2(kw0.y);
        float pa = q4.x * ka0.x + q4.y * ka0.y + q4.z * ka1.x + q4.w * ka1.y;
        pa += __shfl_xor_sync(0xffffffffu, pa, 1);
        pa += __shfl_xor_sync(0xffffffffu, pa, 2);
        pa += __shfl_xor_sync(0xffffffffu, pa, 4);
        float ba = (t0 == 0) ? b0 : ((t0 == 1) ? b1 : b2);
        float ea = __expf(pa * INV_SQRT_HD + ba);
        ssum += ea;
        float2 va0 = unpack_h2(vw0.x);
        float2 va1 = unpack_h2(vw0.y);
        acc.x += ea * va0.x;
        acc.y += ea * va0.y;
        acc.z += ea * va1.x;
        acc.w += ea * va1.y;
    }

    float inv = 1.f / (ssum + 1e-16f);
    float4 o;
    o.x = acc.x * inv; o.y = acc.y * inv; o.z = acc.z * inv; o.w = acc.w * inv;
    ((float4*)g_att)[(size_t)node * 32 + lane] = o;
}

// ---------------------------------------------------------------- K6: out GEMM (tf32 MMA) + LN
// 256 thr / 8 warps. Warp w computes rows [128*bx + 16w, +16) x all 128 cols
// (LN reduction stays within one warp quad). B frags via LDG from g_wo.
__global__ __launch_bounds__(256, 2) void out_ln_kernel(
    const float* __restrict__ x,
    const float* __restrict__ bo,
    const float* __restrict__ gamma, const float* __restrict__ beta,
    float* __restrict__ out, int n)
{
    __shared__ __align__(16) float sX[128][XS];

    int tid  = threadIdx.x;
    int warp = tid >> 5, lane = tid & 31;
    int row0 = blockIdx.x * 128;
    int qr   = lane >> 2;
    int qc   = lane & 3;

    float acc[16][4];
#pragma unroll
    for (int t = 0; t < 16; t++)
#pragma unroll
        for (int j = 0; j < 4; j++) acc[t][j] = 0.f;

    for (int kg0 = 0; kg0 < 128; kg0 += 64) {
        __syncthreads();
#pragma unroll
        for (int t = 0; t < 8; t++) {
            int i = t * 256 + tid;
            int r = i >> 4, c4 = i & 15;
            float4 v = make_float4(0.f, 0.f, 0.f, 0.f);
            if (row0 + r < n)
                v = ((const float4*)g_att)[(size_t)(row0 + r) * 32 + (kg0 >> 2) + c4];
            v.x = tf32r(v.x); v.y = tf32r(v.y); v.z = tf32r(v.z); v.w = tf32r(v.w);
            *((float4*)&sX[r][0] + c4) = v;
        }
        __syncthreads();

#pragma unroll
        for (int k8 = 0; k8 < 64; k8 += 8) {
            int rb = warp * 16;
            unsigned a0 = __float_as_uint(sX[rb + qr][k8 + qc]);
            unsigned a1 = __float_as_uint(sX[rb + qr + 8][k8 + qc]);
            unsigned a2 = __float_as_uint(sX[rb + qr][k8 + qc + 4]);
            unsigned a3 = __float_as_uint(sX[rb + qr + 8][k8 + qc + 4]);
            int kg = kg0 + k8;
            const float* Wr0 = g_wo + (size_t)(kg + qc) * 128 + qr;
            const float* Wr1 = Wr0 + 4 * 128;
#pragma unroll
            for (int t = 0; t < 16; t++) {
                unsigned b0 = __float_as_uint(Wr0[t * 8]);
                unsigned b1 = __float_as_uint(Wr1[t * 8]);
                mma_tf32(acc[t], a0, a1, a2, a3, b0, b1);
            }
        }
    }

    // epilogue: +bias +residual, LayerNorm per row, store.
    // hi = 0 -> row warp*16+qr, hi = 1 -> +8
#pragma unroll
    for (int hi = 0; hi < 2; hi++) {
        int r = row0 + warp * 16 + hi * 8 + qr;
        if (r >= n) continue;

        float sum = 0.f, sq = 0.f;
#pragma unroll
        for (int t = 0; t < 16; t++) {
            int c = t * 8 + qc * 2;
            float2 b2 = *(const float2*)&bo[c];
            float2 xr = *(const float2*)&x[(size_t)r * 128 + c];
            float y0 = acc[t][hi * 2]     + b2.x + xr.x;
            float y1 = acc[t][hi * 2 + 1] + b2.y + xr.y;
            acc[t][hi * 2]     = y0;
            acc[t][hi * 2 + 1] = y1;
            sum += y0 + y1;
            sq  += y0 * y0 + y1 * y1;
        }
        sum += __shfl_xor_sync(0xffffffffu, sum, 1);
        sq  += __shfl_xor_sync(0xffffffffu, sq, 1);
        sum += __shfl_xor_sync(0xffffffffu, sum, 2);
        sq  += __shfl_xor_sync(0xffffffffu, sq, 2);

        float mu   = sum * (1.f / 128.f);
        float var  = sq * (1.f / 128.f) - mu * mu;
        float rstd = rsqrtf(var + 1e-5f);

#pragma unroll
        for (int t = 0; t < 16; t++) {
            int c = t * 8 + qc * 2;
            float2 g2 = *(const float2*)&gamma[c];
            float2 t2 = *(const float2*)&beta[c];
            float2 o;
            o.x = (acc[t][hi * 2]     - mu) * rstd * g2.x + t2.x;
            o.y = (acc[t][hi * 2 + 1] - mu) * rstd * g2.y + t2.y;
            *(float2*)&out[(size_t)r * 128 + c] = o;
        }
    }
}

// ---------------------------------------------------------------- launch
extern "C" void kernel_launch(void* const* d_in, const int* in_sizes, int n_in,
                              void* d_out, int out_size)
{
    const float* x     = (const float*)d_in[0];
    const int*   stype = (const int*)d_in[1];
    const int*   eidx  = (const int*)d_in[2];
    const float* Wq    = (const float*)d_in[3];
    const float* bq    = (const float*)d_in[4];
    const float* Wk    = (const float*)d_in[5];
    const float* bk    = (const float*)d_in[6];
    const float* Wv    = (const float*)d_in[7];
    const float* bv    = (const float*)d_in[8];
    const float* sbias = (const float*)d_in[9];
    const float* Wo    = (const float*)d_in[10];
    const float* bo    = (const float*)d_in[11];
    const float* gam   = (const float*)d_in[12];
    const float* bet   = (const float*)d_in[13];

    int n = in_sizes[0] / 128;
    int e = in_sizes[2] / 2;
    const int* src = eidx;
    const int* dst = eidx + e;

    int nb = (n + SCAN_B - 1) / SCAN_B;
    int gb = (n + 127) / 128;

    // slot #4 (the ncu-captured launch) remains qkv_gemm_kernel.
    zero_cnt_kernel<<<(n + 255) / 256, 256>>>(n);                                  // 1
    hist_kernel<<<(e + 255) / 256, 256>>>(dst, e);                                 // 2
    cvtw_kernel<<<64, 256>>>(Wq, Wk, Wv, Wo);                                      // 3
    qkv_gemm_kernel<<<dim3(gb, 3), 256>>>(x, bq, bk, bv, n);                       // 4 <- profiled
    scan1_kernel<<<nb, SCAN_B>>>(n);                                               // 5
    scan2_kernel<<<1, 64>>>(nb, n);                                                // 6
    scan3_kernel<<<nb, SCAN_B>>>(n);                                               // 7
    scatter_kernel<<<(e + 255) / 256, 256>>>(src, dst, stype, e);                  // 8
    gather_kernel<<<((size_t)n * 32 + 255) / 256, 256>>>(sbias, n);                // 9
    out_ln_kernel<<<gb, 256>>>(x, bo, gam, bet, (float*)d_out, n);                 // 10
}

// round 17
// speedup vs baseline: 1.1629x; 1.1629x over previous
#include <cuda_runtime.h>

// ---------------------------------------------------------------------------
// StructureAwareAttention on GB300 — Round 17: R15 base + m32xn64 qkv warp tile
//   (B-fragment reuse x2 in smem; L1 LDS stream cut 33%; R16's LDG-B reverted)
//   N=50000 nodes, C=128, E=800000 edges, HEADS=4, HEAD_DIM=32
// Launch order keeps qkv in ncu slot #4.
// ---------------------------------------------------------------------------

#define NMAX 50000
#define EMAX 800000
#define SCAN_B 1024

__device__ float    g_q[(size_t)NMAX * 128];
__device__ unsigned g_kh[(size_t)NMAX * 64];   // 64 f16x2 words per row
__device__ unsigned g_vh[(size_t)NMAX * 64];
__device__ float    g_att[(size_t)NMAX * 128];
__device__ int      g_cnt[NMAX];
__device__ int      g_off[NMAX + 1];
__device__ int      g_cur[NMAX];
__device__ int      g_packed[EMAX];
__device__ int      g_bsum[64];
__device__ int      g_boff[64];

// ---------------------------------------------------------------- helpers
__device__ __forceinline__ float tf32r(float f) {
    unsigned u;
    asm("cvt.rna.tf32.f32 %0, %1;" : "=r"(u) : "f"(f));
    return __uint_as_float(u);
}

__device__ __forceinline__ void mma_tf32(float* d,
    unsigned a0, unsigned a1, unsigned a2, unsigned a3,
    unsigned b0, unsigned b1)
{
    asm volatile(
        "mma.sync.aligned.m16n8k8.row.col.f32.tf32.tf32.f32 "
        "{%0,%1,%2,%3}, {%4,%5,%6,%7}, {%8,%9}, {%0,%1,%2,%3};"
        : "+f"(d[0]), "+f"(d[1]), "+f"(d[2]), "+f"(d[3])
        : "r"(a0), "r"(a1), "r"(a2), "r"(a3), "r"(b0), "r"(b1));
}

// pack two fp32 -> one f16x2 word (lo = first arg, hi = second arg)
__device__ __forceinline__ unsigned pack_h2(float lo, float hi) {
    unsigned u;
    asm("cvt.rn.f16x2.f32 %0, %1, %2;" : "=r"(u) : "f"(hi), "f"(lo));
    return u;
}

// unpack f16x2 word -> two fp32
__device__ __forceinline__ float2 unpack_h2(unsigned u) {
    float2 r;
    asm("{\n\t"
        ".reg .b16 l, h;\n\t"
        "mov.b32 {l, h}, %2;\n\t"
        "cvt.f32.f16 %0, l;\n\t"
        "cvt.f32.f16 %1, h;\n\t"
        "}"
        : "=f"(r.x), "=f"(r.y) : "r"(u));
    return r;
}

// SMEM strides for conflict-free fragment LDS:
//   XS=68:  A-frag bank = (lane>>2)*4 + (lane&3)  -> bijection mod 32
//   WS=136: B-frag bank = (lane&3)*8 + (lane>>2)  -> bijection mod 32
#define XS 68
#define WS 136

// ---------------------------------------------------------------- K0: zero
__global__ void zero_cnt_kernel(int n) {
    int i = blockIdx.x * blockDim.x + threadIdx.x;
    if (i < n) g_cnt[i] = 0;
}

// ---------------------------------------------------------------- K1: QKV GEMM (tf32 MMA)
// 256 thr / 8 warps. Warp (mw = warp>>1, nw = warp&1):
//   rows [128*bx + 32*mw, +32) (two m16 tiles), cols [64*nw, +64) (8 n8 tiles).
// B frags from sW smem (conflict-free), reused across the 2 m-tiles.
// blockIdx.y: 0 -> Q (fp32 out), 1 -> K (f16x2 out), 2 -> V (f16x2 out)
__global__ __launch_bounds__(256, 2) void qkv_gemm_kernel(
    const float* __restrict__ x,
    const float* __restrict__ Wq, const float* __restrict__ bq,
    const float* __restrict__ Wk, const float* __restrict__ bk,
    const float* __restrict__ Wv, const float* __restrict__ bv,
    int n)
{
    __shared__ __align__(16) float sX[128][XS];
    __shared__ __align__(16) float sW[16][WS];

    const float* W; const float* bias;
    if (blockIdx.y == 0)      { W = Wq; bias = bq; }
    else if (blockIdx.y == 1) { W = Wk; bias = bk; }
    else                      { W = Wv; bias = bv; }

    int tid  = threadIdx.x;
    int warp = tid >> 5, lane = tid & 31;
    int mw   = warp >> 1;      // 0..3
    int nw   = warp & 1;       // 0..1
    int row0 = blockIdx.x * 128;
    int qr   = lane >> 2;
    int qc   = lane & 3;

    float acc[2][8][4];
#pragma unroll
    for (int m = 0; m < 2; m++)
#pragma unroll
        for (int t = 0; t < 8; t++)
#pragma unroll
            for (int j = 0; j < 4; j++) acc[m][t][j] = 0.f;

    for (int kh = 0; kh < 128; kh += 64) {
        __syncthreads();
        // load X half-tile [128 rows x 64 cols], tf32-rounded (8 float4/thread)
#pragma unroll
        for (int t = 0; t < 8; t++) {
            int i = t * 256 + tid;
            int r = i >> 4, c4 = i & 15;
            float4 v = make_float4(0.f, 0.f, 0.f, 0.f);
            if (row0 + r < n)
                v = ((const float4*)x)[(size_t)(row0 + r) * 32 + (kh >> 2) + c4];
            v.x = tf32r(v.x); v.y = tf32r(v.y); v.z = tf32r(v.z); v.w = tf32r(v.w);
            *((float4*)&sX[r][0] + c4) = v;
        }

        for (int kc = 0; kc < 64; kc += 16) {
            __syncthreads();
#pragma unroll
            for (int t = 0; t < 2; t++) {
                int i = t * 256 + tid;
                int r = i >> 5, c4 = i & 31;
                float4 v = ((const float4*)W)[(size_t)(kh + kc + r) * 32 + c4];
                v.x = tf32r(v.x); v.y = tf32r(v.y); v.z = tf32r(v.z); v.w = tf32r(v.w);
                *((float4*)&sW[r][0] + c4) = v;
            }
            __syncthreads();

#pragma unroll
            for (int ks = 0; ks < 16; ks += 8) {
                int klo = kc + ks;
                // A frags for the warp's two m16 tiles
                unsigned a[2][4];
#pragma unroll
                for (int m = 0; m < 2; m++) {
                    int rb = mw * 32 + m * 16;
                    a[m][0] = __float_as_uint(sX[rb + qr][klo + qc]);
                    a[m][1] = __float_as_uint(sX[rb + qr + 8][klo + qc]);
                    a[m][2] = __float_as_uint(sX[rb + qr][klo + qc + 4]);
                    a[m][3] = __float_as_uint(sX[rb + qr + 8][klo + qc + 4]);
                }
#pragma unroll
                for (int t = 0; t < 8; t++) {
                    unsigned b0 = __float_as_uint(sW[ks + qc][nw * 64 + t * 8 + qr]);
                    unsigned b1 = __float_as_uint(sW[ks + 4 + qc][nw * 64 + t * 8 + qr]);
                    mma_tf32(acc[0][t], a[0][0], a[0][1], a[0][2], a[0][3], b0, b1);
                    mma_tf32(acc[1][t], a[1][0], a[1][1], a[1][2], a[1][3], b0, b1);
                }
            }
        }
    }

    // epilogue: + bias; Q -> fp32, K/V -> packed f16x2
    bool isQ = (blockIdx.y == 0);
    unsigned* outh = (blockIdx.y == 1) ? g_kh : g_vh;
#pragma unroll
    for (int t = 0; t < 8; t++) {
        int c = nw * 64 + t * 8 + qc * 2;
        float2 b2 = *(const float2*)&bias[c];
#pragma unroll
        for (int m = 0; m < 2; m++) {
            int rlo = row0 + mw * 32 + m * 16 + qr;
            int rhi = rlo + 8;
            float2 olo = make_float2(acc[m][t][0] + b2.x, acc[m][t][1] + b2.y);
            float2 ohi = make_float2(acc[m][t][2] + b2.x, acc[m][t][3] + b2.y);
            if (isQ) {
                if (rlo < n) *(float2*)&g_q[(size_t)rlo * 128 + c] = olo;
                if (rhi < n) *(float2*)&g_q[(size_t)rhi * 128 + c] = ohi;
            } else {
                if (rlo < n) outh[(size_t)rlo * 64 + (c >> 1)] = pack_h2(olo.x, olo.y);
                if (rhi < n) outh[(size_t)rhi * 64 + (c >> 1)] = pack_h2(ohi.x, ohi.y);
            }
        }
    }
}

// ---------------------------------------------------------------- K2: histogram
__global__ void hist_kernel(const int* __restrict__ dst, int e) {
    int i = blockIdx.x * blockDim.x + threadIdx.x;
    if (i < e) atomicAdd(&g_cnt[dst[i]], 1);
}

// ---------------------------------------------------------------- S1: block scan
__global__ __launch_bounds__(SCAN_B) void scan1_kernel(int n) {
    __shared__ int wsum[32];
    int tid  = threadIdx.x;
    int lane = tid & 31, wid = tid >> 5;
    int i = blockIdx.x * SCAN_B + tid;
    int val = (i < n) ? g_cnt[i] : 0;

    int x = val;
#pragma unroll
    for (int d = 1; d < 32; d <<= 1) {
        int t = __shfl_up_sync(0xffffffffu, x, d);
        if (lane >= d) x += t;
    }
    if (lane == 31) wsum[wid] = x;
    __syncthreads();
    if (wid == 0) {
        int w = wsum[lane];
#pragma unroll
        for (int d = 1; d < 32; d <<= 1) {
            int t = __shfl_up_sync(0xffffffffu, w, d);
            if (lane >= d) w += t;
        }
        wsum[lane] = w;
    }
    __syncthreads();
    int base = (wid > 0) ? wsum[wid - 1] : 0;
    int incl = x + base;
    if (i < n) g_off[i] = incl - val;
    if (tid == SCAN_B - 1) g_bsum[blockIdx.x] = incl;
}

// ---------------------------------------------------------------- S2: scan blocks
__global__ void scan2_kernel(int nb, int n) {
    __shared__ int s[64];
    int tid = threadIdx.x;
    int val = (tid < nb) ? g_bsum[tid] : 0;
    s[tid] = val;
    __syncthreads();
#pragma unroll
    for (int d = 1; d < 64; d <<= 1) {
        int t = (tid >= d) ? s[tid - d] : 0;
        __syncthreads();
        s[tid] += t;
        __syncthreads();
    }
    if (tid < nb) g_boff[tid] = s[tid] - val;
    if (tid == 63) g_off[n] = s[63];
}

// ---------------------------------------------------------------- S3: add base
__global__ __launch_bounds__(SCAN_B) void scan3_kernel(int n) {
    int i = blockIdx.x * SCAN_B + threadIdx.x;
    if (i < n) {
        int v = g_off[i] + g_boff[blockIdx.x];
        g_off[i] = v;
        g_cur[i] = v;
    }
}

// ---------------------------------------------------------------- K4: scatter
__global__ void scatter_kernel(const int* __restrict__ src,
                               const int* __restrict__ dst,
                               const int* __restrict__ stype, int e) {
    int i = blockIdx.x * blockDim.x + threadIdx.x;
    if (i < e) {
        int d = dst[i];
        int p = atomicAdd(&g_cur[d], 1);
        int s_ = src[i];
        g_packed[p] = s_ | (stype[s_] << 20);
    }
}

// ---------------------------------------------------------------- K5: gather (R7 version)
// One warp per node. Lane l owns dims [4l,4l+4): one uint2 (4 halfs) per matrix.
__global__ __launch_bounds__(256) void gather_kernel(
    const float* __restrict__ sbias, int n)
{
    int node = (blockIdx.x * blockDim.x + threadIdx.x) >> 5;
    int lane = threadIdx.x & 31;
    if (node >= n) return;

    int head = lane >> 3;
    float b0 = sbias[0 * 4 + head];
    float b1 = sbias[1 * 4 + head];
    float b2 = sbias[2 * 4 + head];

    const uint2* kp = (const uint2*)g_kh;   // node row = 32 uint2
    const uint2* vp = (const uint2*)g_vh;
    float4 q4 = ((const float4*)g_q)[(size_t)node * 32 + lane];

    float4 acc = make_float4(0.f, 0.f, 0.f, 0.f);
    float ssum = 0.f;
    const float INV_SQRT_HD = 0.17677669529663689f;  // 1/sqrt(32)

    int beg = g_off[node], end = g_off[node + 1];
    int j = beg;
    for (; j + 1 < end; j += 2) {
        int w0 = g_packed[j], w1 = g_packed[j + 1];
        int s0 = w0 & 0xFFFFF, t0 = w0 >> 20;
        int s1 = w1 & 0xFFFFF, t1 = w1 >> 20;
        uint2 kw0 = kp[(size_t)s0 * 32 + lane];
        uint2 kw1 = kp[(size_t)s1 * 32 + lane];
        uint2 vw0 = vp[(size_t)s0 * 32 + lane];
        uint2 vw1 = vp[(size_t)s1 * 32 + lane];

        float2 ka0 = unpack_h2(kw0.x);
        float2 ka1 = unpack_h2(kw0.y);
        float2 kb0 = unpack_h2(kw1.x);
        float2 kb1 = unpack_h2(kw1.y);

        float pa = q4.x * ka0.x + q4.y * ka0.y + q4.z * ka1.x + q4.w * ka1.y;
        float pb = q4.x * kb0.x + q4.y * kb0.y + q4.z * kb1.x + q4.w * kb1.y;
        pa += __shfl_xor_sync(0xffffffffu, pa, 1);
        pb += __shfl_xor_sync(0xffffffffu, pb, 1);
        pa += __shfl_xor_sync(0xffffffffu, pa, 2);
        pb += __shfl_xor_sync(0xffffffffu, pb, 2);
        pa += __shfl_xor_sync(0xffffffffu, pa, 4);
        pb += __shfl_xor_sync(0xffffffffu, pb, 4);

        float ba = (t0 == 0) ? b0 : ((t0 == 1) ? b1 : b2);
        float bb = (t1 == 0) ? b0 : ((t1 == 1) ? b1 : b2);
        float ea = __expf(pa * INV_SQRT_HD + ba);
        float eb = __expf(pb * INV_SQRT_HD + bb);
        ssum += ea + eb;

        float2 va0 = unpack_h2(vw0.x);
        float2 va1 = unpack_h2(vw0.y);
        float2 vb0 = unpack_h2(vw1.x);
        float2 vb1 = unpack_h2(vw1.y);
        acc.x += ea * va0.x + eb * vb0.x;
        acc.y += ea * va0.y + eb * vb0.y;
        acc.z += ea * va1.x + eb * vb1.x;
        acc.w += ea * va1.y + eb * vb1.y;
    }
    if (j < end) {
        int w0 = g_packed[j];
        int s0 = w0 & 0xFFFFF, t0 = w0 >> 20;
        uint2 kw0 = kp[(size_t)s0 * 32 + lane];
        uint2 vw0 = vp[(size_t)s0 * 32 + lane];
        float2 ka0 = unpack_h2(kw0.x);
        float2 ka1 = unpack_h2(kw0.y);
        float pa = q4.x * ka0.x + q4.y * ka0.y + q4.z * ka1.x + q4.w * ka1.y;
        pa += __shfl_xor_sync(0xffffffffu, pa, 1);
        pa += __shfl_xor_sync(0xffffffffu, pa, 2);
        pa += __shfl_xor_sync(0xffffffffu, pa, 4);
        float ba = (t0 == 0) ? b0 : ((t0 == 1) ? b1 : b2);
        float ea = __expf(pa * INV_SQRT_HD + ba);
        ssum += ea;
        float2 va0 = unpack_h2(vw0.x);
        float2 va1 = unpack_h2(vw0.y);
        acc.x += ea * va0.x;
        acc.y += ea * va0.y;
        acc.z += ea * va1.x;
        acc.w += ea * va1.y;
    }

    float inv = 1.f / (ssum + 1e-16f);
    float4 o;
    o.x = acc.x * inv; o.y = acc.y * inv; o.z = acc.z * inv; o.w = acc.w * inv;
    ((float4*)g_att)[(size_t)node * 32 + lane] = o;
}

// ---------------------------------------------------------------- K6: out GEMM (tf32 MMA) + LN
// 256 thr / 8 warps. Warp w computes rows [128*bx + 16w, +16) x all 128 cols,
// so each row's LN reduction stays within one warp quad. (R15 version.)
__global__ __launch_bounds__(256, 2) void out_ln_kernel(
    const float* __restrict__ x,
    const float* __restrict__ Wo, const float* __restrict__ bo,
    const float* __restrict__ gamma, const float* __restrict__ beta,
    float* __restrict__ out, int n)
{
    __shared__ __align__(16) float sX[128][XS];
    __shared__ __align__(16) float sW[16][WS];

    int tid  = threadIdx.x;
    int warp = tid >> 5, lane = tid & 31;
    int row0 = blockIdx.x * 128;
    int qr   = lane >> 2;
    int qc   = lane & 3;

    float acc[16][4];
#pragma unroll
    for (int t = 0; t < 16; t++)
#pragma unroll
        for (int j = 0; j < 4; j++) acc[t][j] = 0.f;

    for (int kh = 0; kh < 128; kh += 64) {
        __syncthreads();
#pragma unroll
        for (int t = 0; t < 8; t++) {
            int i = t * 256 + tid;
            int r = i >> 4, c4 = i & 15;
            float4 v = make_float4(0.f, 0.f, 0.f, 0.f);
            if (row0 + r < n)
                v = ((const float4*)g_att)[(size_t)(row0 + r) * 32 + (kh >> 2) + c4];
            v.x = tf32r(v.x); v.y = tf32r(v.y); v.z = tf32r(v.z); v.w = tf32r(v.w);
            *((float4*)&sX[r][0] + c4) = v;
        }

        for (int kc = 0; kc < 64; kc += 16) {
            __syncthreads();
#pragma unroll
            for (int t = 0; t < 2; t++) {
                int i = t * 256 + tid;
                int r = i >> 5, c4 = i & 31;
                float4 v = ((const float4*)Wo)[(size_t)(kh + kc + r) * 32 + c4];
                v.x = tf32r(v.x); v.y = tf32r(v.y); v.z = tf32r(v.z); v.w = tf32r(v.w);
                *((float4*)&sW[r][0] + c4) = v;
            }
            __syncthreads();

#pragma unroll
            for (int ks = 0; ks < 16; ks += 8) {
                int klo = kc + ks;
                int rb = warp * 16;
                unsigned a0 = __float_as_uint(sX[rb + qr][klo + qc]);
                unsigned a1 = __float_as_uint(sX[rb + qr + 8][klo + qc]);
                unsigned a2 = __float_as_uint(sX[rb + qr][klo + qc + 4]);
                unsigned a3 = __float_as_uint(sX[rb + qr + 8][klo + qc + 4]);
#pragma unroll
                for (int t = 0; t < 16; t++) {
                    unsigned b0 = __float_as_uint(sW[ks + qc][t * 8 + qr]);
                    unsigned b1 = __float_as_uint(sW[ks + 4 + qc][t * 8 + qr]);
                    mma_tf32(acc[t], a0, a1, a2, a3, b0, b1);
                }
            }
        }
    }

    // epilogue: +bias +residual, LayerNorm per row, store.
    // hi = 0 -> row warp*16+qr, hi = 1 -> +8
#pragma unroll
    for (int hi = 0; hi < 2; hi++) {
        int r = row0 + warp * 16 + hi * 8 + qr;
        if (r >= n) continue;

        float sum = 0.f, sq = 0.f;
#pragma unroll
        for (int t = 0; t < 16; t++) {
            int c = t * 8 + qc * 2;
            float2 b2 = *(const float2*)&bo[c];
            float2 xr = *(const float2*)&x[(size_t)r * 128 + c];
            float y0 = acc[t][hi * 2]     + b2.x + xr.x;
            float y1 = acc[t][hi * 2 + 1] + b2.y + xr.y;
            acc[t][hi * 2]     = y0;
            acc[t][hi * 2 + 1] = y1;
            sum += y0 + y1;
            sq  += y0 * y0 + y1 * y1;
        }
        sum += __shfl_xor_sync(0xffffffffu, sum, 1);
        sq  += __shfl_xor_sync(0xffffffffu, sq, 1);
        sum += __shfl_xor_sync(0xffffffffu, sum, 2);
        sq  += __shfl_xor_sync(0xffffffffu, sq, 2);

        float mu   = sum * (1.f / 128.f);
        float var  = sq * (1.f / 128.f) - mu * mu;
        float rstd = rsqrtf(var + 1e-5f);

#pragma unroll
        for (int t = 0; t < 16; t++) {
            int c = t * 8 + qc * 2;
            float2 g2 = *(const float2*)&gamma[c];
            float2 t2 = *(const float2*)&beta[c];
            float2 o;
            o.x = (acc[t][hi * 2]     - mu) * rstd * g2.x + t2.x;
            o.y = (acc[t][hi * 2 + 1] - mu) * rstd * g2.y + t2.y;
            *(float2*)&out[(size_t)r * 128 + c] = o;
        }
    }
}

// ---------------------------------------------------------------- launch
extern "C" void kernel_launch(void* const* d_in, const int* in_sizes, int n_in,
                              void* d_out, int out_size)
{
    const float* x     = (const float*)d_in[0];
    const int*   stype = (const int*)d_in[1];
    const int*   eidx  = (const int*)d_in[2];
    const float* Wq    = (const float*)d_in[3];
    const float* bq    = (const float*)d_in[4];
    const float* Wk    = (const float*)d_in[5];
    const float* bk    = (const float*)d_in[6];
    const float* Wv    = (const float*)d_in[7];
    const float* bv    = (const float*)d_in[8];
    const float* sbias = (const float*)d_in[9];
    const float* Wo    = (const float*)d_in[10];
    const float* bo    = (const float*)d_in[11];
    const float* gam   = (const float*)d_in[12];
    const float* bet   = (const float*)d_in[13];

    int n = in_sizes[0] / 128;
    int e = in_sizes[2] / 2;
    const int* src = eidx;
    const int* dst = eidx + e;

    int nb = (n + SCAN_B - 1) / SCAN_B;
    int gb = (n + 127) / 128;

    // slot #4 (the ncu-captured launch) remains qkv_gemm_kernel.
    zero_cnt_kernel<<<(n + 255) / 256, 256>>>(n);                                  // 1
    hist_kernel<<<(e + 255) / 256, 256>>>(dst, e);                                 // 2
    scan1_kernel<<<nb, SCAN_B>>>(n);                                               // 3
    qkv_gemm_kernel<<<dim3(gb, 3), 256>>>(x, Wq, bq, Wk, bk, Wv, bv, n);           // 4 <- profiled
    scan2_kernel<<<1, 64>>>(nb, n);                                                // 5
    scan3_kernel<<<nb, SCAN_B>>>(n);                                               // 6
    scatter_kernel<<<(e + 255) / 256, 256>>>(src, dst, stype, e);                  // 7
    gather_kernel<<<((size_t)n * 32 + 255) / 256, 256>>>(sbias, n);                // 8
    out_ln_kernel<<<gb, 256>>>(x, Wo, bo, gam, bet, (float*)d_out, n);             // 9
}